// round 3
// baseline (speedup 1.0000x reference)
#include <cuda_runtime.h>
#include <cuda_bf16.h>

// Shapes fixed by setup_inputs
#define BATCH 8
#define L 128
#define D 768
#define NF4 (D / 4)                  // 192 float4 per row
#define NROW (BATCH * L * L)         // 131072
#define PER_B (L * L)                // 16384
#define K1_BLOCKS 2048
#define K1_WARPS 8
#define QPW 2                        // quads (4 rows) per warp

// Device scratch (no allocations allowed)
__device__ float g_logS[NROW];
__device__ float g_logE[NROW];
__device__ float g_losspart[16];

// order-preserving float->uint encoding (monotonic over all floats)
__device__ __forceinline__ unsigned enc_f32(float f)
{
    unsigned u = __float_as_uint(f);
    return (u & 0x80000000u) ? ~u : (u | 0x80000000u);
}

// ---------------------------------------------------------------------------
// K1: pure streaming dual GEMV. Each warp: 4 rows in parallel (8 lanes/row,
// 24 float4/lane, contiguous 128B per lane-group). Epilogue is only 3 shuffle
// steps + one 8B store -> minimal serial exposure between load bursts.
// ---------------------------------------------------------------------------
__global__ __launch_bounds__(256) void k_main(
    const float* __restrict__ table,
    const float* __restrict__ W_S,
    const float* __restrict__ W_E)
{
    __shared__ float4 sWs[NF4];
    __shared__ float4 sWe[NF4];

    for (int i = threadIdx.x; i < NF4; i += 256) {
        sWs[i] = ((const float4*)W_S)[i];
        sWe[i] = ((const float4*)W_E)[i];
    }
    __syncthreads();

    const int warp = threadIdx.x >> 5;
    const int lane = threadIdx.x & 31;
    const int sub  = lane >> 3;       // row within quad (0..3)
    const int o    = lane & 7;        // float4 base offset (0..7)
    const int gw   = blockIdx.x * K1_WARPS + warp;

#pragma unroll
    for (int qq = 0; qq < QPW; qq++) {
        const long long row = ((long long)gw * QPW + qq) * 4 + sub;
        const float4* __restrict__ t = (const float4*)table + row * NF4;

        float sS = 0.f, sE = 0.f;
#pragma unroll
        for (int j = 0; j < 24; j++) {
            const int idx = o + 8 * j;
            const float4 v = __ldcs(&t[idx]);
            const float4 a = sWs[idx];
            const float4 b = sWe[idx];
            sS += v.x * a.x + v.y * a.y + v.z * a.z + v.w * a.w;
            sE += v.x * b.x + v.y * b.y + v.z * b.z + v.w * b.w;
        }
#pragma unroll
        for (int off = 1; off < 8; off <<= 1) {
            sS += __shfl_xor_sync(0xFFFFFFFFu, sS, off);
            sE += __shfl_xor_sync(0xFFFFFFFFu, sE, off);
        }
        if (o == 0) {
            g_logS[row] = sS;   // raw sums; bias added in k_sel
            g_logE[row] = sE;
        }
    }
}

// ---------------------------------------------------------------------------
// K2: per-(batch, head) block. Reads logits + labels (L2-resident), computes
// BCE partial + encoded keys in registers, radix-selects the exact k-th
// largest key with warp-private match_any histograms (no atomics) and a
// parallel suffix scan, then writes the predict mask.
// blockIdx.x: [0,8) = S head (batch b), [8,16) = E head.
// out layout: [loss_S, loss_E, predict_S(131072), predict_E(131072)]
// ---------------------------------------------------------------------------
__global__ __launch_bounds__(512) void k_sel(
    const int* __restrict__ amask,
    const int* __restrict__ labS, const int* __restrict__ labE,
    const float* __restrict__ bSp, const float* __restrict__ bEp,
    float* __restrict__ out)
{
    const int b    = blockIdx.x & 7;
    const int head = blockIdx.x >> 3;     // 0=S, 1=E
    const int tid  = threadIdx.x;
    const int lane = tid & 31;
    const int warp = tid >> 5;

    const float bias = head ? bEp[0] : bSp[0];
    const float* __restrict__ lg   = (head ? g_logE : g_logS) + b * PER_B;
    const int*   __restrict__ tgt  = (head ? labE : labS) + b * PER_B;
    const int*   __restrict__ wsrc = labS + b * PER_B;   // weight uses labS for BOTH heads

    unsigned key[32];
    float lossAcc = 0.f;
#pragma unroll
    for (int i = 0; i < 32; i++) {
        const int idx = tid + 512 * i;
        const float l = lg[idx] + bias;
        const int   t = tgt[idx];
        const float w = (wsrc[idx] >= 0) ? 1.0f : 0.0f;
        lossAcc += w * (fmaxf(l, 0.f) - l * (float)t + log1pf(expf(-fabsf(l))));
        key[i] = enc_f32(w / (1.0f + expf(-l)));
    }

    // ---- deterministic block reduction of loss partial ----
    __shared__ float s_red[16];
#pragma unroll
    for (int off = 16; off; off >>= 1)
        lossAcc += __shfl_xor_sync(0xFFFFFFFFu, lossAcc, off);
    if (lane == 0) s_red[warp] = lossAcc;
    __syncthreads();
    if (tid == 0) {
        float s = 0.f;
#pragma unroll
        for (int i = 0; i < 16; i++) s += s_red[i];
        g_losspart[blockIdx.x] = s;
    }

    // ---- compute k (span pruning length) ----
    __shared__ int      s_kk;
    __shared__ unsigned s_prefix, s_pmask;
    if (tid == 0) {
        int msum = 0;
        for (int i = 0; i < L; i++) msum += amask[b * L + i];
        const int mlen = msum - 2;
        int len = (int)((float)mlen * 0.3f);   // trunc like .astype(int32)
        if (len < 5) len = 5;
        const int mlsq = mlen * mlen;
        if (len > mlsq) len = mlsq;
        if (len < 1) len = 1;
        if (len > PER_B) len = PER_B;
        s_kk = len;
        s_prefix = 0u;
        s_pmask  = 0u;
    }

    // ---- 4-pass radix select, no atomics ----
    __shared__ int whist[16 * 257];   // warp-private histograms (+ sentinel bin)
    __shared__ int s_suf[256];
    __syncthreads();

    for (int pass = 3; pass >= 0; pass--) {
        const int shift = pass * 8;
        for (int i = tid; i < 16 * 257; i += 512) whist[i] = 0;
        __syncthreads();
        const unsigned pm = s_pmask;
        const unsigned pf = s_prefix;
        int* wh = whist + warp * 257;
#pragma unroll
        for (int i = 0; i < 32; i++) {
            const unsigned bin = ((key[i] & pm) == pf) ? ((key[i] >> shift) & 0xFFu) : 256u;
            const unsigned peers = __match_any_sync(0xFFFFFFFFu, bin);
            if (bin < 256u && (int)(__ffs(peers) - 1) == lane)
                wh[bin] += __popc(peers);          // leader-only, warp-private: no race
        }
        __syncthreads();

        // reduce across warps into s_suf, then inclusive suffix-sum
        if (tid < 256) {
            int s = 0;
#pragma unroll
            for (int w = 0; w < 16; w++) s += whist[w * 257 + tid];
            s_suf[tid] = s;
        }
        __syncthreads();
        for (int off = 1; off < 256; off <<= 1) {
            int v = 0;
            if (tid < 256) {
                v = s_suf[tid];
                if (tid + off < 256) v += s_suf[tid + off];
            }
            __syncthreads();
            if (tid < 256) s_suf[tid] = v;
            __syncthreads();
        }
        // pick the largest bin c with suffix(c) >= k  (exactly one thread matches)
        if (tid < 256) {
            const int k   = s_kk;
            const int nxt = (tid == 255) ? 0 : s_suf[tid + 1];
            if (s_suf[tid] >= k && nxt < k) {
                s_prefix = pf | ((unsigned)tid << shift);
                s_pmask  = pm | (0xFFu << shift);
                s_kk     = k - nxt;
            }
        }
        __syncthreads();
    }

    // s_prefix == encoded k-th largest key; key >= thr is bit-identical
    // to the reference's pred >= topkth comparison
    const unsigned thr = s_prefix;
    float* __restrict__ o = out + 2 + head * NROW + b * PER_B;
#pragma unroll
    for (int i = 0; i < 32; i++)
        o[tid + 512 * i] = (key[i] >= thr) ? 1.0f : 0.0f;
}

// ---------------------------------------------------------------------------
// K3: final loss combine
// ---------------------------------------------------------------------------
__global__ void k_fin(float* __restrict__ out)
{
    if (threadIdx.x == 0) {
        float s = 0.f, e = 0.f;
#pragma unroll
        for (int i = 0; i < 8; i++) { s += g_losspart[i]; e += g_losspart[8 + i]; }
        out[0] = s / (float)NROW;
        out[1] = e / (float)NROW;
    }
}

// ---------------------------------------------------------------------------
extern "C" void kernel_launch(void* const* d_in, const int* in_sizes, int n_in,
                              void* d_out, int out_size)
{
    const float* table = (const float*)d_in[0];
    const int*   amask = (const int*)d_in[1];
    const int*   labS  = (const int*)d_in[2];
    const int*   labE  = (const int*)d_in[3];
    const float* W_S   = (const float*)d_in[4];
    const float* b_S   = (const float*)d_in[5];
    const float* W_E   = (const float*)d_in[6];
    const float* b_E   = (const float*)d_in[7];
    float* out = (float*)d_out;

    k_main<<<K1_BLOCKS, 256>>>(table, W_S, W_E);
    k_sel<<<16, 512>>>(amask, labS, labE, b_S, b_E, out);
    k_fin<<<1, 32>>>(out);
}

// round 4
// speedup vs baseline: 1.2175x; 1.2175x over previous
#include <cuda_runtime.h>
#include <cuda_bf16.h>

// Shapes fixed by setup_inputs
#define BATCH 8
#define L 128
#define D 768
#define NF4 (D / 4)                  // 192 float4 per row
#define NROW (BATCH * L * L)         // 131072
#define PER_B (L * L)                // 16384
#define NQUAD (NROW / 4)             // 32768
#define GRID1 592                    // 148 SMs x 4 blocks: one wave
#define TOTW (GRID1 * 8)             // 4736 warps

// Device scratch (no allocations allowed)
__device__ float    g_logS[NROW];
__device__ float    g_logE[NROW];
__device__ unsigned g_keyS[NROW];
__device__ unsigned g_keyE[NROW];
__device__ float    g_lpS[256];
__device__ float    g_lpE[256];

// order-preserving float->uint encoding (monotonic over all floats)
__device__ __forceinline__ unsigned enc_f32(float f)
{
    unsigned u = __float_as_uint(f);
    return (u & 0x80000000u) ? ~u : (u | 0x80000000u);
}

// ---------------------------------------------------------------------------
// K1: pure streaming dual GEMV, single-wave grid-stride.
// Warp handles 4 rows/quad: 8 lanes/row, 24 float4/lane (contiguous 128B per
// 8-lane group). Split accumulators halve the FMA dependency chain.
// ---------------------------------------------------------------------------
__global__ __launch_bounds__(256) void k_main(
    const float* __restrict__ table,
    const float* __restrict__ W_S,
    const float* __restrict__ W_E)
{
    __shared__ float4 sWs[NF4];
    __shared__ float4 sWe[NF4];

    for (int i = threadIdx.x; i < NF4; i += 256) {
        sWs[i] = ((const float4*)W_S)[i];
        sWe[i] = ((const float4*)W_E)[i];
    }
    __syncthreads();

    const int warp = threadIdx.x >> 5;
    const int lane = threadIdx.x & 31;
    const int sub  = lane >> 3;       // row within quad (0..3)
    const int o    = lane & 7;        // float4 base offset (0..7)
    const int gw   = blockIdx.x * 8 + warp;

    for (int q = gw; q < NQUAD; q += TOTW) {
        const long long row = (long long)q * 4 + sub;
        const float4* __restrict__ t = (const float4*)table + row * NF4;

        float s0 = 0.f, s1 = 0.f, e0 = 0.f, e1 = 0.f;
#pragma unroll
        for (int j = 0; j < 24; j += 2) {
            const int i0 = o + 8 * j;
            const int i1 = i0 + 8;
            const float4 v0 = __ldcs(&t[i0]);
            const float4 v1 = __ldcs(&t[i1]);
            const float4 a0 = sWs[i0], b0 = sWe[i0];
            const float4 a1 = sWs[i1], b1 = sWe[i1];
            s0 += v0.x * a0.x + v0.y * a0.y + v0.z * a0.z + v0.w * a0.w;
            e0 += v0.x * b0.x + v0.y * b0.y + v0.z * b0.z + v0.w * b0.w;
            s1 += v1.x * a1.x + v1.y * a1.y + v1.z * a1.z + v1.w * a1.w;
            e1 += v1.x * b1.x + v1.y * b1.y + v1.z * b1.z + v1.w * b1.w;
        }
        float sS = s0 + s1;
        float sE = e0 + e1;
#pragma unroll
        for (int off = 1; off < 8; off <<= 1) {
            sS += __shfl_xor_sync(0xFFFFFFFFu, sS, off);
            sE += __shfl_xor_sync(0xFFFFFFFFu, sE, off);
        }
        if (o == 0) {                     // lanes 0,8,16,24 -> 4 consecutive rows
            g_logS[row] = sS;
            g_logE[row] = sE;
        }
    }
}

// ---------------------------------------------------------------------------
// K2: whole-chip elementwise pass: BCE partials + encoded sigmoid keys.
// Fast intrinsics (__expf/__logf): rel err ~1e-6 vs 1e-3 tolerance.
// ---------------------------------------------------------------------------
__global__ __launch_bounds__(512) void k_prep(
    const int* __restrict__ labS, const int* __restrict__ labE,
    const float* __restrict__ bSp, const float* __restrict__ bEp)
{
    const int i    = blockIdx.x * 512 + threadIdx.x;
    const int lane = threadIdx.x & 31;
    const int warp = threadIdx.x >> 5;

    const float lS = g_logS[i] + bSp[0];
    const float lE = g_logE[i] + bEp[0];
    const int   tS = labS[i];
    const int   tE = labE[i];
    const float w  = (tS >= 0) ? 1.0f : 0.0f;

    const float aS = __expf(-fabsf(lS));
    const float aE = __expf(-fabsf(lE));
    float bceS = w * (fmaxf(lS, 0.f) - lS * (float)tS + __logf(1.f + aS));
    float bceE = w * (fmaxf(lE, 0.f) - lE * (float)tE + __logf(1.f + aE));

    g_keyS[i] = enc_f32(w / (1.f + __expf(-lS)));
    g_keyE[i] = enc_f32(w / (1.f + __expf(-lE)));

    // deterministic block partial sums
    __shared__ float rS[16], rE[16];
#pragma unroll
    for (int off = 16; off; off >>= 1) {
        bceS += __shfl_xor_sync(0xFFFFFFFFu, bceS, off);
        bceE += __shfl_xor_sync(0xFFFFFFFFu, bceE, off);
    }
    if (lane == 0) { rS[warp] = bceS; rE[warp] = bceE; }
    __syncthreads();
    if (threadIdx.x == 0) {
        float a = 0.f, b = 0.f;
#pragma unroll
        for (int k = 0; k < 16; k++) { a += rS[k]; b += rE[k]; }
        g_lpS[blockIdx.x] = a;
        g_lpE[blockIdx.x] = b;
    }
}

// ---------------------------------------------------------------------------
// K3: per-(batch, head) exact k-th-largest radix select + mask write.
// Keys held in registers; warp-private match_any histograms (no atomics);
// single-warp shuffle suffix-scan (2 BARs per pass).
// blockIdx.x: [0,8)=S, [8,16)=E.
// out layout: [loss_S, loss_E, predict_S(131072), predict_E(131072)]
// ---------------------------------------------------------------------------
__global__ __launch_bounds__(512) void k_sel(const int* __restrict__ amask,
                                             float* __restrict__ out)
{
    const int b    = blockIdx.x & 7;
    const int head = blockIdx.x >> 3;
    const int tid  = threadIdx.x;
    const int lane = tid & 31;
    const int warp = tid >> 5;

    const unsigned* __restrict__ keys = (head ? g_keyE : g_keyS) + b * PER_B;

    unsigned key[32];
#pragma unroll
    for (int i = 0; i < 32; i++) key[i] = keys[tid + 512 * i];

    __shared__ int      whist[16 * 257];
    __shared__ int      s_suf[256];
    __shared__ int      s_kk;
    __shared__ unsigned s_prefix, s_pmask;

    // span-pruning k, computed by warp 0
    if (warp == 0) {
        int m = amask[b * L + lane] + amask[b * L + 32 + lane]
              + amask[b * L + 64 + lane] + amask[b * L + 96 + lane];
#pragma unroll
        for (int off = 16; off; off >>= 1) m += __shfl_xor_sync(0xFFFFFFFFu, m, off);
        if (lane == 0) {
            const int mlen = m - 2;
            int len = (int)((float)mlen * 0.3f);   // trunc like .astype(int32)
            if (len < 5) len = 5;
            const int mlsq = mlen * mlen;
            if (len > mlsq) len = mlsq;
            if (len < 1) len = 1;
            if (len > PER_B) len = PER_B;
            s_kk = len;
            s_prefix = 0u;
            s_pmask  = 0u;
        }
    }
    __syncthreads();

    for (int pass = 3; pass >= 0; pass--) {
        const int shift = pass * 8;
        for (int i = tid; i < 16 * 257; i += 512) whist[i] = 0;
        __syncthreads();

        const unsigned pm = s_pmask;
        const unsigned pf = s_prefix;
        int* wh = whist + warp * 257;
#pragma unroll
        for (int i = 0; i < 32; i++) {
            const unsigned bin = ((key[i] & pm) == pf) ? ((key[i] >> shift) & 0xFFu) : 256u;
            const unsigned peers = __match_any_sync(0xFFFFFFFFu, bin);
            if (bin < 256u && (int)(__ffs(peers) - 1) == lane)
                wh[bin] += __popc(peers);          // warp-private: no race
        }
        __syncthreads();

        if (tid < 256) {
            int s = 0;
#pragma unroll
            for (int w = 0; w < 16; w++) s += whist[w * 257 + tid];
            s_suf[tid] = s;
        }
        __syncthreads();

        // warp 0: suffix scan over 256 bins (8 bins/lane) + winner pick
        if (warp == 0) {
            const int k = s_kk;
            int v[8], ls[8];
#pragma unroll
            for (int i = 0; i < 8; i++) v[i] = s_suf[lane * 8 + i];
            ls[7] = v[7];
#pragma unroll
            for (int i = 6; i >= 0; i--) ls[i] = ls[i + 1] + v[i];
            int T = ls[0];
            int S = T;
#pragma unroll
            for (int off = 1; off < 32; off <<= 1) {
                const int u = __shfl_down_sync(0xFFFFFFFFu, S, off);
                if (lane + off < 32) S += u;
            }
            const int E = S - T;   // sum over bins in higher lanes
#pragma unroll
            for (int i = 0; i < 8; i++) {
                const int suf = ls[i] + E;
                const int nxt = (i < 7) ? (ls[i + 1] + E) : E;
                if (suf >= k && nxt < k) {          // exactly one (lane,i) matches
                    s_prefix = pf | ((unsigned)(lane * 8 + i) << shift);
                    s_pmask  = pm | (0xFFu << shift);
                    s_kk     = k - nxt;
                }
            }
        }
        __syncthreads();
    }

    // s_prefix == encoded k-th largest key (bit-exact); key >= thr matches
    // the reference's pred >= topkth comparison
    const unsigned thr = s_prefix;
    float* __restrict__ o = out + 2 + head * NROW + b * PER_B;
#pragma unroll
    for (int i = 0; i < 32; i++)
        o[tid + 512 * i] = (key[i] >= thr) ? 1.0f : 0.0f;
}

// ---------------------------------------------------------------------------
// K4: final loss combine (deterministic tree)
// ---------------------------------------------------------------------------
__global__ __launch_bounds__(256) void k_fin(float* __restrict__ out)
{
    __shared__ float sA[256], sB[256];
    const int tid = threadIdx.x;
    sA[tid] = g_lpS[tid];
    sB[tid] = g_lpE[tid];
    __syncthreads();
    for (int s = 128; s; s >>= 1) {
        if (tid < s) { sA[tid] += sA[tid + s]; sB[tid] += sB[tid + s]; }
        __syncthreads();
    }
    if (tid == 0) {
        out[0] = sA[0] / (float)NROW;
        out[1] = sB[0] / (float)NROW;
    }
}

// ---------------------------------------------------------------------------
extern "C" void kernel_launch(void* const* d_in, const int* in_sizes, int n_in,
                              void* d_out, int out_size)
{
    const float* table = (const float*)d_in[0];
    const int*   amask = (const int*)d_in[1];
    const int*   labS  = (const int*)d_in[2];
    const int*   labE  = (const int*)d_in[3];
    const float* W_S   = (const float*)d_in[4];
    const float* b_S   = (const float*)d_in[5];
    const float* W_E   = (const float*)d_in[6];
    const float* b_E   = (const float*)d_in[7];
    float* out = (float*)d_out;

    k_main<<<GRID1, 256>>>(table, W_S, W_E);
    k_prep<<<256, 512>>>(labS, labE, b_S, b_E);
    k_sel<<<16, 512>>>(amask, out);
    k_fin<<<1, 256>>>(out);
}

// round 5
// speedup vs baseline: 1.4361x; 1.1796x over previous
#include <cuda_runtime.h>
#include <cuda_bf16.h>

// Shapes fixed by setup_inputs
#define BATCH 8
#define L 128
#define D 768
#define NF4 (D / 4)                  // 192 float4 per row
#define NROW (BATCH * L * L)         // 131072
#define PER_B (L * L)                // 16384
#define NQUAD (NROW / 4)             // 32768
#define GRID1 592                    // 148 SMs x 4 blocks: one wave
#define TOTW (GRID1 * 8)             // 4736 warps

// Device scratch (no allocations allowed)
__device__ float2   g_part[NROW * 8];   // per-(row, lane-group) partials, 8MB
__device__ unsigned g_keyS[NROW];
__device__ unsigned g_keyE[NROW];
__device__ float    g_lpS[256];
__device__ float    g_lpE[256];

// order-preserving float->uint encoding (monotonic over all floats)
__device__ __forceinline__ unsigned enc_f32(float f)
{
    unsigned u = __float_as_uint(f);
    return (u & 0x80000000u) ? ~u : (u | 0x80000000u);
}

// ---------------------------------------------------------------------------
// K1: pure streaming dual GEMV with NO cross-lane dependency.
// Warp covers 4 rows (8 lanes/row, 24 float4/lane). Each lane stores its own
// (sS,sE) partial as one 8B float2 -> no shuffles, no reduce, no drain bubble
// between quads; the warp's next load burst issues immediately.
// ---------------------------------------------------------------------------
__global__ __launch_bounds__(256) void k_main(
    const float* __restrict__ table,
    const float* __restrict__ W_S,
    const float* __restrict__ W_E)
{
    __shared__ float4 sWs[NF4];
    __shared__ float4 sWe[NF4];

    for (int i = threadIdx.x; i < NF4; i += 256) {
        sWs[i] = ((const float4*)W_S)[i];
        sWe[i] = ((const float4*)W_E)[i];
    }
    __syncthreads();

    const int warp = threadIdx.x >> 5;
    const int lane = threadIdx.x & 31;
    const int sub  = lane >> 3;       // row within quad (0..3)
    const int o    = lane & 7;        // float4 base offset (0..7)
    const int gw   = blockIdx.x * 8 + warp;

    for (int q = gw; q < NQUAD; q += TOTW) {
        const long long row = (long long)q * 4 + sub;
        const float4* __restrict__ t = (const float4*)table + row * NF4;

        float s0 = 0.f, s1 = 0.f, e0 = 0.f, e1 = 0.f;
#pragma unroll
        for (int j = 0; j < 24; j += 2) {
            const int i0 = o + 8 * j;
            const int i1 = i0 + 8;
            const float4 v0 = __ldcs(&t[i0]);
            const float4 v1 = __ldcs(&t[i1]);
            const float4 a0 = sWs[i0], b0 = sWe[i0];
            const float4 a1 = sWs[i1], b1 = sWe[i1];
            s0 += v0.x * a0.x + v0.y * a0.y + v0.z * a0.z + v0.w * a0.w;
            e0 += v0.x * b0.x + v0.y * b0.y + v0.z * b0.z + v0.w * b0.w;
            s1 += v1.x * a1.x + v1.y * a1.y + v1.z * a1.z + v1.w * a1.w;
            e1 += v1.x * b1.x + v1.y * b1.y + v1.z * b1.z + v1.w * b1.w;
        }
        // one independent 8B store per lane; warp stores 4x64B segments
        g_part[row * 8 + o] = make_float2(s0 + s1, e0 + e1);
    }
}

// ---------------------------------------------------------------------------
// K2: whole-chip pass: reduce 8 lane-partials per row, add bias, BCE partial
// sums + encoded sigmoid keys. One thread per row; 64B contiguous per thread.
// Fast intrinsics (__expf/__logf): rel err ~1e-6 vs 1e-3 tolerance.
// ---------------------------------------------------------------------------
__global__ __launch_bounds__(512) void k_prep(
    const int* __restrict__ labS, const int* __restrict__ labE,
    const float* __restrict__ bSp, const float* __restrict__ bEp)
{
    const int i    = blockIdx.x * 512 + threadIdx.x;   // row id
    const int lane = threadIdx.x & 31;
    const int warp = threadIdx.x >> 5;

    const float4* __restrict__ p = (const float4*)(g_part + (long long)i * 8);
    float sS = 0.f, sE = 0.f;
#pragma unroll
    for (int k = 0; k < 4; k++) {
        const float4 v = p[k];      // (sS_k0, sE_k0, sS_k1, sE_k1)
        sS += v.x + v.z;
        sE += v.y + v.w;
    }

    const float lS = sS + bSp[0];
    const float lE = sE + bEp[0];
    const int   tS = labS[i];
    const int   tE = labE[i];
    const float w  = (tS >= 0) ? 1.0f : 0.0f;

    float bceS = w * (fmaxf(lS, 0.f) - lS * (float)tS + __logf(1.f + __expf(-fabsf(lS))));
    float bceE = w * (fmaxf(lE, 0.f) - lE * (float)tE + __logf(1.f + __expf(-fabsf(lE))));

    g_keyS[i] = enc_f32(w / (1.f + __expf(-lS)));
    g_keyE[i] = enc_f32(w / (1.f + __expf(-lE)));

    // deterministic block partial sums
    __shared__ float rS[16], rE[16];
#pragma unroll
    for (int off = 16; off; off >>= 1) {
        bceS += __shfl_xor_sync(0xFFFFFFFFu, bceS, off);
        bceE += __shfl_xor_sync(0xFFFFFFFFu, bceE, off);
    }
    if (lane == 0) { rS[warp] = bceS; rE[warp] = bceE; }
    __syncthreads();
    if (threadIdx.x == 0) {
        float a = 0.f, b = 0.f;
#pragma unroll
        for (int k = 0; k < 16; k++) { a += rS[k]; b += rE[k]; }
        g_lpS[blockIdx.x] = a;
        g_lpE[blockIdx.x] = b;
    }
}

// ---------------------------------------------------------------------------
// K3: blocks 0-15: per-(batch, head) exact k-th-largest radix select + mask
// write (keys in registers, match_any histograms, warp suffix-scan).
// block 16: final loss reduction -> out[0], out[1].
// out layout: [loss_S, loss_E, predict_S(131072), predict_E(131072)]
// ---------------------------------------------------------------------------
__global__ __launch_bounds__(512) void k_sel(const int* __restrict__ amask,
                                             float* __restrict__ out)
{
    const int tid  = threadIdx.x;
    const int lane = tid & 31;
    const int warp = tid >> 5;

    if (blockIdx.x == 16) {
        __shared__ float sA[256], sB[256];
        if (tid < 256) { sA[tid] = g_lpS[tid]; sB[tid] = g_lpE[tid]; }
        __syncthreads();
        for (int s = 128; s; s >>= 1) {
            if (tid < s) { sA[tid] += sA[tid + s]; sB[tid] += sB[tid + s]; }
            __syncthreads();
        }
        if (tid == 0) {
            out[0] = sA[0] / (float)NROW;
            out[1] = sB[0] / (float)NROW;
        }
        return;
    }

    const int b    = blockIdx.x & 7;
    const int head = blockIdx.x >> 3;
    const unsigned* __restrict__ keys = (head ? g_keyE : g_keyS) + b * PER_B;

    unsigned key[32];
#pragma unroll
    for (int i = 0; i < 32; i++) key[i] = keys[tid + 512 * i];

    __shared__ int      whist[16 * 257];
    __shared__ int      s_suf[256];
    __shared__ int      s_kk;
    __shared__ unsigned s_prefix, s_pmask;

    // span-pruning k, computed by warp 0
    if (warp == 0) {
        int m = amask[b * L + lane] + amask[b * L + 32 + lane]
              + amask[b * L + 64 + lane] + amask[b * L + 96 + lane];
#pragma unroll
        for (int off = 16; off; off >>= 1) m += __shfl_xor_sync(0xFFFFFFFFu, m, off);
        if (lane == 0) {
            const int mlen = m - 2;
            int len = (int)((float)mlen * 0.3f);   // trunc like .astype(int32)
            if (len < 5) len = 5;
            const int mlsq = mlen * mlen;
            if (len > mlsq) len = mlsq;
            if (len < 1) len = 1;
            if (len > PER_B) len = PER_B;
            s_kk = len;
            s_prefix = 0u;
            s_pmask  = 0u;
        }
    }
    __syncthreads();

    for (int pass = 3; pass >= 0; pass--) {
        const int shift = pass * 8;
        for (int i = tid; i < 16 * 257; i += 512) whist[i] = 0;
        __syncthreads();

        const unsigned pm = s_pmask;
        const unsigned pf = s_prefix;
        int* wh = whist + warp * 257;
#pragma unroll
        for (int i = 0; i < 32; i++) {
            const unsigned bin = ((key[i] & pm) == pf) ? ((key[i] >> shift) & 0xFFu) : 256u;
            const unsigned peers = __match_any_sync(0xFFFFFFFFu, bin);
            if (bin < 256u && (int)(__ffs(peers) - 1) == lane)
                wh[bin] += __popc(peers);          // warp-private: no race
        }
        __syncthreads();

        if (tid < 256) {
            int s = 0;
#pragma unroll
            for (int w = 0; w < 16; w++) s += whist[w * 257 + tid];
            s_suf[tid] = s;
        }
        __syncthreads();

        // warp 0: suffix scan over 256 bins (8 bins/lane) + winner pick
        if (warp == 0) {
            const int k = s_kk;
            int v[8], ls[8];
#pragma unroll
            for (int i = 0; i < 8; i++) v[i] = s_suf[lane * 8 + i];
            ls[7] = v[7];
#pragma unroll
            for (int i = 6; i >= 0; i--) ls[i] = ls[i + 1] + v[i];
            int T = ls[0];
            int S = T;
#pragma unroll
            for (int off = 1; off < 32; off <<= 1) {
                const int u = __shfl_down_sync(0xFFFFFFFFu, S, off);
                if (lane + off < 32) S += u;
            }
            const int E = S - T;   // sum over bins in higher lanes
#pragma unroll
            for (int i = 0; i < 8; i++) {
                const int suf = ls[i] + E;
                const int nxt = (i < 7) ? (ls[i + 1] + E) : E;
                if (suf >= k && nxt < k) {          // exactly one (lane,i) matches
                    s_prefix = pf | ((unsigned)(lane * 8 + i) << shift);
                    s_pmask  = pm | (0xFFu << shift);
                    s_kk     = k - nxt;
                }
            }
        }
        __syncthreads();
    }

    // s_prefix == encoded k-th largest key (bit-exact); key >= thr matches
    // the reference's pred >= topkth comparison
    const unsigned thr = s_prefix;
    float* __restrict__ o = out + 2 + head * NROW + b * PER_B;
#pragma unroll
    for (int i = 0; i < 32; i++)
        o[tid + 512 * i] = (key[i] >= thr) ? 1.0f : 0.0f;
}

// ---------------------------------------------------------------------------
extern "C" void kernel_launch(void* const* d_in, const int* in_sizes, int n_in,
                              void* d_out, int out_size)
{
    const float* table = (const float*)d_in[0];
    const int*   amask = (const int*)d_in[1];
    const int*   labS  = (const int*)d_in[2];
    const int*   labE  = (const int*)d_in[3];
    const float* W_S   = (const float*)d_in[4];
    const float* b_S   = (const float*)d_in[5];
    const float* W_E   = (const float*)d_in[6];
    const float* b_E   = (const float*)d_in[7];
    float* out = (float*)d_out;

    k_main<<<GRID1, 256>>>(table, W_S, W_E);
    k_prep<<<256, 512>>>(labS, labE, b_S, b_E);
    k_sel<<<17, 512>>>(amask, out);
}